// round 16
// baseline (speedup 1.0000x reference)
#include <cuda_runtime.h>
#include <cuda_fp16.h>
#include <cstdint>
#include <math.h>

#define B_   8192
#define D_   2048
#define K_   256
#define ALPHA_ 1000.0f

// ---------------------------------------------------------------------------
// Device scratch (no cudaMalloc allowed)
// ---------------------------------------------------------------------------
__device__ float g_emb[B_ * K_];
__device__ float g_dist[B_ * K_];   // G' = -2 e.c + ||c||^2
__device__ float g_enorm[B_];
__device__ float g_cnorm[K_];
// fp16 2-level splits
__device__ __half g_xh[B_ * D_];    // x
__device__ __half g_xl[B_ * D_];
__device__ __half g_weh[K_ * D_];   // W_enc^T * 64
__device__ __half g_wel[K_ * D_];
__device__ __half g_wdh[D_ * K_];   // W_dec^T * 16
__device__ __half g_wdl[D_ * K_];
__device__ __half g_eh[B_ * K_];    // emb (written by GEMM1 epilogue)
__device__ __half g_el[B_ * K_];
__device__ __half g_crh[K_ * K_];   // cluster_reps * 16
__device__ __half g_crl[K_ * K_];

// ---------------------------------------------------------------------------
// Helpers
// ---------------------------------------------------------------------------
__device__ __forceinline__ uint32_t smem_u32(const void* p) {
    uint32_t a;
    asm("{ .reg .u64 t; cvta.to.shared.u64 t, %1; cvt.u32.u64 %0, t; }"
        : "=r"(a) : "l"(p));
    return a;
}

__device__ __forceinline__ void cp_async16(uint32_t dst, const void* src) {
    asm volatile("cp.async.cg.shared.global [%0], [%1], 16;"
                 :: "r"(dst), "l"(src) : "memory");
}
#define CP_COMMIT() asm volatile("cp.async.commit_group;" ::: "memory")
#define CP_WAIT(N)  asm volatile("cp.async.wait_group %0;" :: "n"(N) : "memory")

__device__ __forceinline__ void ldm_x4(uint32_t* r, uint32_t addr) {
    asm volatile("ldmatrix.sync.aligned.m8n8.x4.shared.b16 {%0,%1,%2,%3}, [%4];"
                 : "=r"(r[0]), "=r"(r[1]), "=r"(r[2]), "=r"(r[3]) : "r"(addr));
}

__device__ __forceinline__ void mma16816(float* c, const uint32_t* a,
                                         uint32_t b0, uint32_t b1) {
    asm volatile(
        "mma.sync.aligned.m16n8k16.row.col.f32.f16.f16.f32 "
        "{%0,%1,%2,%3}, {%4,%5,%6,%7}, {%8,%9}, {%0,%1,%2,%3};"
        : "+f"(c[0]), "+f"(c[1]), "+f"(c[2]), "+f"(c[3])
        : "r"(a[0]), "r"(a[1]), "r"(a[2]), "r"(a[3]), "r"(b0), "r"(b1));
}

// ---------------------------------------------------------------------------
// Split kernels (fp16 2-level): v*scale = h + l
// ---------------------------------------------------------------------------
__global__ __launch_bounds__(256) void split2h(
    const float* __restrict__ in, __half* __restrict__ h,
    __half* __restrict__ l, float scale, int n4)
{
    int i = blockIdx.x * 256 + threadIdx.x;
    if (i >= n4) return;
    float4 v = ((const float4*)in)[i];
    float vv[4] = {v.x * scale, v.y * scale, v.z * scale, v.w * scale};
    __half hh[4], ll[4];
#pragma unroll
    for (int j = 0; j < 4; j++) {
        hh[j] = __float2half_rn(vv[j]);
        ll[j] = __float2half_rn(vv[j] - __half2float(hh[j]));
    }
    __half2* H = (__half2*)h;
    __half2* L = (__half2*)l;
    H[2 * i]     = __halves2half2(hh[0], hh[1]);
    H[2 * i + 1] = __halves2half2(hh[2], hh[3]);
    L[2 * i]     = __halves2half2(ll[0], ll[1]);
    L[2 * i + 1] = __halves2half2(ll[2], ll[3]);
}

// Transpose + scale + split: out[r, c] = split(in[c, r] * scale)
__global__ __launch_bounds__(256) void wt_split(
    const float* __restrict__ in, __half* __restrict__ h,
    __half* __restrict__ l, float scale, int rows_out, int cols_out)
{
    int idx = blockIdx.x * 256 + threadIdx.x;
    if (idx >= rows_out * cols_out) return;
    int r = idx / cols_out;
    int c = idx % cols_out;
    float v = in[(size_t)c * rows_out + r] * scale;
    __half hf = __float2half_rn(v);
    h[idx] = hf;
    l[idx] = __float2half_rn(v - __half2float(hf));
}

// ---------------------------------------------------------------------------
// FUSED split HMMA GEMM (single K traversal, NPROD products per slab):
//   NPROD==3: C = scale * (Ah@Bh^T + Ah@Bl^T + Al@Bh^T) + bias   (22-bit grade)
//   NPROD==2: C = scale * (Ah@Bh^T + Ah@Bl^T) + bias             (~5e-4 grade;
//             Al never loaded — fewer cp.async and ldsm)
// fp16 operands, fp32 accumulate, periodic RN drain of the mma accumulator
// (every 2 slabs) to bound the tensor-core RZ-accumulate bias.
// CTA tile 64x128, BK=32, 2-stage cp.async, 48 KB smem, 2 CTAs/SM.
// 4 warps as 1(m) x 4(n); warp tile 64x32 via m16n8k16.
// Optional epilogue outputs Ch/Cl = fp16 2-level split of C (for chaining).
// grid = (N/128, M/64), 128 threads.
// ---------------------------------------------------------------------------
template <int NPROD>
__global__ __launch_bounds__(128, 2) void hmma_gemmf(
    const __half* __restrict__ Ah, const __half* __restrict__ Al,
    const __half* __restrict__ Bh, const __half* __restrict__ Bl,
    const float* __restrict__ bias, float* __restrict__ C,
    __half* __restrict__ Ch, __half* __restrict__ Cl,
    int Kdim, int Ncols, float scale)
{
    // [buf][ Ah 4096 | Al 4096 | Bh 8192 | Bl 8192 ] = 24576; x2 = 49152 B
    __shared__ __align__(16) unsigned char sm[2][24576];

    const int tid  = threadIdx.x;
    const int lane = tid & 31;
    const int wid  = tid >> 5;          // 0..3
    const int wn   = wid * 32;          // warp n offset
    const size_t arow0 = (size_t)blockIdx.y * 64;
    const size_t bcol0 = (size_t)blockIdx.x * 128;

    const int ns = Kdim / 32;

    float acc[4][4][4];     // short-chain mma accumulator
    float mst[4][4][4];     // master fp32 accumulator (RN adds)
#pragma unroll
    for (int i = 0; i < 4; i++)
#pragma unroll
        for (int j = 0; j < 4; j++)
#pragma unroll
            for (int r = 0; r < 4; r++) { acc[i][j][r] = 0.0f; mst[i][j][r] = 0.0f; }

    // --- slab loader: Ah (+Al) 64x32, Bh+Bl 128x32 fp16, swizzled chunks ---
    auto load_slab = [&](int s, int buf) {
        const int k0 = s * 32;
        const uint32_t sb = smem_u32(&sm[buf][0]);
        const __half* Ahb = Ah + arow0 * Kdim + k0;
        const __half* Alb = Al + arow0 * Kdim + k0;
        const __half* Bhb = Bh + bcol0 * Kdim + k0;
        const __half* Blb = Bl + bcol0 * Kdim + k0;
        // A tiles: 64 rows x 4 chunks = 256 chunks each, 2 per thread
#pragma unroll
        for (int t = 0; t < 2; t++) {
            const int idx = tid + t * 128;          // 0..255
            const int row = idx >> 2;
            const int c   = idx & 3;
            const uint32_t off = row * 64 + ((c ^ (row & 3)) * 16);
            cp_async16(sb + off, Ahb + (size_t)row * Kdim + c * 8);
            if (NPROD == 3)
                cp_async16(sb + 4096 + off, Alb + (size_t)row * Kdim + c * 8);
        }
        // B tiles: 128 rows x 4 chunks = 512 chunks each, 4 per thread
#pragma unroll
        for (int t = 0; t < 4; t++) {
            const int idx = tid + t * 128;          // 0..511
            const int row = idx >> 2;
            const int c   = idx & 3;
            const uint32_t off = row * 64 + ((c ^ (row & 3)) * 16);
            cp_async16(sb + 8192 + off,  Bhb + (size_t)row * Kdim + c * 8);
            cp_async16(sb + 16384 + off, Blb + (size_t)row * Kdim + c * 8);
        }
        CP_COMMIT();
    };

    load_slab(0, 0);

    for (int s = 0; s < ns; s++) {
        if (s + 1 < ns) {
            load_slab(s + 1, (s + 1) & 1);
            CP_WAIT(1);
        } else {
            CP_WAIT(0);
        }
        __syncthreads();

        const uint32_t sb  = smem_u32(&sm[s & 1][0]);
        const uint32_t sAh = sb, sAl = sb + 4096;
        const uint32_t sBh = sb + 8192, sBl = sb + 16384;
        const int rl = (lane & 7) + ((lane >> 3) & 1) * 8;  // row-in-16 for ldmatrix

#pragma unroll
        for (int s16 = 0; s16 < 2; s16++) {
            const int ch = s16 * 2 + (lane >> 4);           // 16B chunk (k8 index)
            uint32_t ah[4][4], al[4][4], bh[2][4], bl[2][4];
#pragma unroll
            for (int i = 0; i < 4; i++) {
                const int row = i * 16 + rl;                // wm = 0
                const uint32_t off = row * 64 + ((ch ^ (row & 3)) * 16);
                ldm_x4(ah[i], sAh + off);
                if (NPROD == 3) ldm_x4(al[i], sAl + off);
            }
#pragma unroll
            for (int j = 0; j < 2; j++) {
                const int row = wn + j * 16 + rl;
                const uint32_t off = row * 64 + ((ch ^ (row & 3)) * 16);
                ldm_x4(bh[j], sBh + off);
                ldm_x4(bl[j], sBl + off);
            }
            // Products into the same accumulator: hh + hl (+ lh)
#pragma unroll
            for (int i = 0; i < 4; i++)
#pragma unroll
                for (int nn = 0; nn < 4; nn++) {
                    const int h = nn >> 1;
                    const uint32_t bh0 = (nn & 1) ? bh[h][1] : bh[h][0];
                    const uint32_t bh1 = (nn & 1) ? bh[h][3] : bh[h][2];
                    const uint32_t bl0 = (nn & 1) ? bl[h][1] : bl[h][0];
                    const uint32_t bl1 = (nn & 1) ? bl[h][3] : bl[h][2];
                    mma16816(acc[i][nn], ah[i], bh0, bh1);
                    mma16816(acc[i][nn], ah[i], bl0, bl1);
                    if (NPROD == 3) mma16816(acc[i][nn], al[i], bh0, bh1);
                }
        }

        // Drain every 2 slabs: master += acc (RN), acc = 0.
        if (((s & 1) == 1) || (s + 1 == ns)) {
#pragma unroll
            for (int i = 0; i < 4; i++)
#pragma unroll
                for (int j = 0; j < 4; j++)
#pragma unroll
                    for (int r = 0; r < 4; r++) {
                        mst[i][j][r] += acc[i][j][r];
                        acc[i][j][r] = 0.0f;
                    }
        }
        __syncthreads();
    }

    // --- epilogue: scale + bias; optional fp16 2-level split outputs ---
    const int mrow  = lane >> 2;
    const int ncol2 = (lane & 3) * 2;
#pragma unroll
    for (int nn = 0; nn < 4; nn++) {
        const int n = (int)bcol0 + wn + nn * 8 + ncol2;
        const float2 bv = *(const float2*)(bias + n);
#pragma unroll
        for (int i = 0; i < 4; i++) {
            const size_t m0 = arow0 + i * 16 + mrow;
            float2 o0, o1;
            o0.x = mst[i][nn][0] * scale + bv.x;
            o0.y = mst[i][nn][1] * scale + bv.y;
            o1.x = mst[i][nn][2] * scale + bv.x;
            o1.y = mst[i][nn][3] * scale + bv.y;
            *(float2*)(C + m0 * Ncols + n)       = o0;
            *(float2*)(C + (m0 + 8) * Ncols + n) = o1;
            if (Ch) {
                __half h0x = __float2half_rn(o0.x), h0y = __float2half_rn(o0.y);
                __half h1x = __float2half_rn(o1.x), h1y = __float2half_rn(o1.y);
                *(__half2*)(Ch + m0 * Ncols + n) = __halves2half2(h0x, h0y);
                *(__half2*)(Ch + (m0 + 8) * Ncols + n) = __halves2half2(h1x, h1y);
                *(__half2*)(Cl + m0 * Ncols + n) = __halves2half2(
                    __float2half_rn(o0.x - __half2float(h0x)),
                    __float2half_rn(o0.y - __half2float(h0y)));
                *(__half2*)(Cl + (m0 + 8) * Ncols + n) = __halves2half2(
                    __float2half_rn(o1.x - __half2float(h1x)),
                    __float2half_rn(o1.y - __half2float(h1y)));
            }
        }
    }
}

// ---------------------------------------------------------------------------
// Row-wise squared norms for [rows, 256] fp32. One warp per row.
// ---------------------------------------------------------------------------
__global__ void rownorm256(const float* __restrict__ src, float* __restrict__ dst,
                           int rows)
{
    const int gw   = (blockIdx.x * blockDim.x + threadIdx.x) >> 5;
    const int lane = threadIdx.x & 31;
    if (gw >= rows) return;
    const float4* p = (const float4*)(src + (size_t)gw * 256);
    float4 a = p[lane];
    float4 b = p[lane + 32];
    float s = a.x * a.x + a.y * a.y + a.z * a.z + a.w * a.w
            + b.x * b.x + b.y * b.y + b.z * b.z + b.w * b.w;
#pragma unroll
    for (int o = 16; o > 0; o >>= 1) s += __shfl_xor_sync(0xffffffffu, s, o);
    if (lane == 0) dst[gw] = s;
}

// ---------------------------------------------------------------------------
// Softmin epilogue: G[b,k] = -2 e.c + ||c||^2 from the tensor GEMM.
// dist = enorm[b] + G; stable softmin over k; outWD[k,b] = dist*softmax.
// ---------------------------------------------------------------------------
__global__ __launch_bounds__(256) void softmin_lite(
    const float* __restrict__ G, const float* __restrict__ enorm,
    float* __restrict__ outWD)
{
    __shared__ float stage[128 * 65];   // 33 KB
    const int tid  = threadIdx.x;
    const int lane = tid & 31;
    const int wid  = tid >> 5;
    const int b0   = blockIdx.x * 64;

    float wd[8][8];
#pragma unroll
    for (int i = 0; i < 8; i++) {
        const int b = b0 + wid * 8 + i;
        const float en = enorm[b];
        const float* Gr = G + (size_t)b * K_;
        float dd[8];
        float m = INFINITY;
#pragma unroll
        for (int c = 0; c < 8; c++) {
            dd[c] = en + Gr[lane + 32 * c];
            m = fminf(m, dd[c]);
        }
#pragma unroll
        for (int o = 16; o > 0; o >>= 1)
            m = fminf(m, __shfl_xor_sync(0xffffffffu, m, o));

        float e[8];
        float s = 0.0f;
#pragma unroll
        for (int c = 0; c < 8; c++) {
            e[c] = expf(-ALPHA_ * (dd[c] - m));
            s += e[c];
        }
#pragma unroll
        for (int o = 16; o > 0; o >>= 1)
            s += __shfl_xor_sync(0xffffffffu, s, o);
        const float inv = 1.0f / s;
#pragma unroll
        for (int c = 0; c < 8; c++)
            wd[i][c] = dd[c] * e[c] * inv;
    }

    // stage + coalesced store in two 128-k-row halves (stage = [128][65])
#pragma unroll
    for (int hh = 0; hh < 2; hh++) {
        if (hh) __syncthreads();
#pragma unroll
        for (int i = 0; i < 8; i++)
#pragma unroll
            for (int cc = 0; cc < 4; cc++) {
                const int c = hh * 4 + cc;
                stage[(lane + 32 * c - 128 * hh) * 65 + wid * 8 + i] = wd[i][c];
            }
        __syncthreads();
#pragma unroll
        for (int t = 0; t < 8; t++) {
            const int idx = tid + t * 256;      // 0..2047
            const int k   = idx >> 4;           // 0..127
            const int c4  = idx & 15;
            float4 o;
            o.x = stage[k * 65 + c4 * 4 + 0];
            o.y = stage[k * 65 + c4 * 4 + 1];
            o.z = stage[k * 65 + c4 * 4 + 2];
            o.w = stage[k * 65 + c4 * 4 + 3];
            *(float4*)(outWD + (size_t)(128 * hh + k) * B_ + b0 + c4 * 4) = o;
        }
    }
}

// ---------------------------------------------------------------------------
// Launch
// ---------------------------------------------------------------------------
extern "C" void kernel_launch(void* const* d_in, const int* in_sizes, int n_in,
                              void* d_out, int out_size)
{
    const float* x     = (const float*)d_in[0];  // [B, D]
    const float* W_enc = (const float*)d_in[1];  // [D, K]
    const float* b_enc = (const float*)d_in[2];  // [K]
    const float* W_dec = (const float*)d_in[3];  // [K, D]
    const float* b_dec = (const float*)d_in[4];  // [D]
    const float* CR    = (const float*)d_in[5];  // [K, K]

    float* out    = (float*)d_out;
    float* outWD  = out;                         // [K, B]
    float* outRec = out + (size_t)K_ * B_;       // [B, D]

    float *emb, *dist, *en, *cn;
    __half *xh, *xl, *weh, *wel, *wdh, *wdl, *eh, *el, *crh, *crl;
    cudaGetSymbolAddress((void**)&emb,  g_emb);
    cudaGetSymbolAddress((void**)&dist, g_dist);
    cudaGetSymbolAddress((void**)&en,   g_enorm);
    cudaGetSymbolAddress((void**)&cn,   g_cnorm);
    cudaGetSymbolAddress((void**)&xh,   g_xh);
    cudaGetSymbolAddress((void**)&xl,   g_xl);
    cudaGetSymbolAddress((void**)&weh,  g_weh);
    cudaGetSymbolAddress((void**)&wel,  g_wel);
    cudaGetSymbolAddress((void**)&wdh,  g_wdh);
    cudaGetSymbolAddress((void**)&wdl,  g_wdl);
    cudaGetSymbolAddress((void**)&eh,   g_eh);
    cudaGetSymbolAddress((void**)&el,   g_el);
    cudaGetSymbolAddress((void**)&crh,  g_crh);
    cudaGetSymbolAddress((void**)&crl,  g_crl);

    // 1) fp16 2-level splits (weights transposed + exponent pre-scaled;
    //    CR row-major, scaled x16 so the low split stays fp16-normal)
    split2h<<<(B_ * D_ / 4 + 255) / 256, 256>>>(x, xh, xl, 1.0f, B_ * D_ / 4);
    wt_split<<<(K_ * D_ + 255) / 256, 256>>>(W_enc, weh, wel, 64.0f, K_, D_);
    wt_split<<<(D_ * K_ + 255) / 256, 256>>>(W_dec, wdh, wdl, 16.0f, D_, K_);
    split2h<<<(K_ * K_ / 4 + 255) / 256, 256>>>(CR, crh, crl, 16.0f, K_ * K_ / 4);

    // 2) emb = x @ W_enc + b_enc  (3 products — amplified path, /64);
    //    epilogue also emits eh/el = fp16 split of emb
    hmma_gemmf<3><<<dim3(K_ / 128, B_ / 64), 128>>>(
        xh, xl, weh, wel, b_enc, emb, eh, el, D_, K_, 1.0f / 64.0f);

    // 3) norms
    rownorm256<<<B_ / 8, 256>>>(emb, en, B_);
    rownorm256<<<K_ / 8, 256>>>(CR, cn, K_);

    // 4) G = -2 e.c^T + ||c||^2 via tensor GEMM (3 products — amplified path)
    hmma_gemmf<3><<<dim3(K_ / 128, B_ / 64), 128>>>(
        eh, el, crh, crl, cn, dist, nullptr, nullptr, K_, K_, -0.125f);

    // 5) recon = emb @ W_dec + b_dec  (2 products — 1e-3 tolerance path, /16)
    hmma_gemmf<2><<<dim3(D_ / 128, B_ / 64), 128>>>(
        eh, el, wdh, wdl, b_dec, outRec, nullptr, nullptr, K_, D_, 1.0f / 16.0f);

    // 6) softmin epilogue: dist = en + G, stable softmin, transposed store
    softmin_lite<<<B_ / 64, 256>>>(dist, en, outWD);
}

// round 17
// speedup vs baseline: 1.5095x; 1.5095x over previous
#include <cuda_runtime.h>
#include <cuda_fp16.h>
#include <cstdint>
#include <math.h>

#define B_   8192
#define D_   2048
#define K_   256
#define ALPHA_ 1000.0f

// ---------------------------------------------------------------------------
// Device scratch (no cudaMalloc allowed)
// ---------------------------------------------------------------------------
__device__ float g_emb[B_ * K_];
__device__ float g_dist[B_ * K_];   // G' = -2 e.c + ||c||^2
__device__ float g_enorm[B_];
__device__ float g_cnorm[K_];
// fp16 2-level splits
__device__ __half g_xh[B_ * D_];    // x
__device__ __half g_xl[B_ * D_];
__device__ __half g_weh[K_ * D_];   // W_enc^T * 64
__device__ __half g_wel[K_ * D_];
__device__ __half g_wdh[D_ * K_];   // W_dec^T * 16
__device__ __half g_wdl[D_ * K_];
__device__ __half g_eh[B_ * K_];    // emb (written by GEMM1 epilogue)
__device__ __half g_el[B_ * K_];
__device__ __half g_crh[K_ * K_];   // cluster_reps * 16
__device__ __half g_crl[K_ * K_];

// ---------------------------------------------------------------------------
// Helpers
// ---------------------------------------------------------------------------
__device__ __forceinline__ uint32_t smem_u32(const void* p) {
    uint32_t a;
    asm("{ .reg .u64 t; cvta.to.shared.u64 t, %1; cvt.u32.u64 %0, t; }"
        : "=r"(a) : "l"(p));
    return a;
}

__device__ __forceinline__ void cp_async16(uint32_t dst, const void* src) {
    asm volatile("cp.async.cg.shared.global [%0], [%1], 16;"
                 :: "r"(dst), "l"(src) : "memory");
}
#define CP_COMMIT() asm volatile("cp.async.commit_group;" ::: "memory")
#define CP_WAIT(N)  asm volatile("cp.async.wait_group %0;" :: "n"(N) : "memory")

__device__ __forceinline__ void ldm_x4(uint32_t* r, uint32_t addr) {
    asm volatile("ldmatrix.sync.aligned.m8n8.x4.shared.b16 {%0,%1,%2,%3}, [%4];"
                 : "=r"(r[0]), "=r"(r[1]), "=r"(r[2]), "=r"(r[3]) : "r"(addr));
}

__device__ __forceinline__ void mma16816(float* c, const uint32_t* a,
                                         uint32_t b0, uint32_t b1) {
    asm volatile(
        "mma.sync.aligned.m16n8k16.row.col.f32.f16.f16.f32 "
        "{%0,%1,%2,%3}, {%4,%5,%6,%7}, {%8,%9}, {%0,%1,%2,%3};"
        : "+f"(c[0]), "+f"(c[1]), "+f"(c[2]), "+f"(c[3])
        : "r"(a[0]), "r"(a[1]), "r"(a[2]), "r"(a[3]), "r"(b0), "r"(b1));
}

// ---------------------------------------------------------------------------
// Merged split kernel: one launch handles all four split jobs.
//   seg0: x       elementwise, n4 = B*D/4 quads        (16384 blocks)
//   seg1: W_enc^T transpose + x64, K*D elems           (2048 blocks)
//   seg2: W_dec^T transpose + x16, D*K elems           (2048 blocks)
//   seg3: CR      elementwise x16, n4 = K*K/4 quads    (64 blocks)
// ---------------------------------------------------------------------------
#define SPLIT_B0 16384
#define SPLIT_B1 (SPLIT_B0 + 2048)
#define SPLIT_B2 (SPLIT_B1 + 2048)
#define SPLIT_B3 (SPLIT_B2 + 64)

__device__ __forceinline__ void split_quad(
    const float* __restrict__ in, __half* __restrict__ h,
    __half* __restrict__ l, float scale, int i)
{
    float4 v = ((const float4*)in)[i];
    float vv[4] = {v.x * scale, v.y * scale, v.z * scale, v.w * scale};
    __half hh[4], ll[4];
#pragma unroll
    for (int j = 0; j < 4; j++) {
        hh[j] = __float2half_rn(vv[j]);
        ll[j] = __float2half_rn(vv[j] - __half2float(hh[j]));
    }
    __half2* H = (__half2*)h;
    __half2* L = (__half2*)l;
    H[2 * i]     = __halves2half2(hh[0], hh[1]);
    H[2 * i + 1] = __halves2half2(hh[2], hh[3]);
    L[2 * i]     = __halves2half2(ll[0], ll[1]);
    L[2 * i + 1] = __halves2half2(ll[2], ll[3]);
}

__device__ __forceinline__ void split_T(
    const float* __restrict__ in, __half* __restrict__ h,
    __half* __restrict__ l, float scale, int rows_out, int cols_out, int idx)
{
    int r = idx / cols_out;
    int c = idx % cols_out;
    float v = in[(size_t)c * rows_out + r] * scale;
    __half hf = __float2half_rn(v);
    h[idx] = hf;
    l[idx] = __float2half_rn(v - __half2float(hf));
}

__global__ __launch_bounds__(256) void split_all(
    const float* __restrict__ x, const float* __restrict__ W_enc,
    const float* __restrict__ W_dec, const float* __restrict__ CR,
    __half* __restrict__ xh, __half* __restrict__ xl,
    __half* __restrict__ weh, __half* __restrict__ wel,
    __half* __restrict__ wdh, __half* __restrict__ wdl,
    __half* __restrict__ crh, __half* __restrict__ crl)
{
    const int bid = blockIdx.x;
    if (bid < SPLIT_B0) {
        split_quad(x, xh, xl, 1.0f, bid * 256 + threadIdx.x);
    } else if (bid < SPLIT_B1) {
        split_T(W_enc, weh, wel, 64.0f, K_, D_,
                (bid - SPLIT_B0) * 256 + threadIdx.x);
    } else if (bid < SPLIT_B2) {
        split_T(W_dec, wdh, wdl, 16.0f, D_, K_,
                (bid - SPLIT_B1) * 256 + threadIdx.x);
    } else {
        split_quad(CR, crh, crl, 16.0f, (bid - SPLIT_B2) * 256 + threadIdx.x);
    }
}

// ---------------------------------------------------------------------------
// FUSED split HMMA GEMM (single K traversal, NPROD products per slab):
//   NPROD==3: C = scale * (Ah@Bh^T + Ah@Bl^T + Al@Bh^T) + bias   (22-bit grade)
//   NPROD==2: C = scale * (Ah@Bh^T + Ah@Bl^T) + bias             (~5e-4 grade;
//             Al never loaded — fewer cp.async and ldsm)
// fp16 operands, fp32 accumulate, periodic RN drain of the mma accumulator
// (every 2 slabs) to bound the tensor-core RZ-accumulate bias.
// CTA tile 64x128, BK=32, 2-stage cp.async, 48 KB smem, 2 CTAs/SM.
// 4 warps as 1(m) x 4(n); warp tile 64x32 via m16n8k16.
// Optional epilogue outputs Ch/Cl = fp16 2-level split of C (for chaining).
// grid = (N/128, M/64), 128 threads.
// ---------------------------------------------------------------------------
template <int NPROD>
__global__ __launch_bounds__(128, 2) void hmma_gemmf(
    const __half* __restrict__ Ah, const __half* __restrict__ Al,
    const __half* __restrict__ Bh, const __half* __restrict__ Bl,
    const float* __restrict__ bias, float* __restrict__ C,
    __half* __restrict__ Ch, __half* __restrict__ Cl,
    int Kdim, int Ncols, float scale)
{
    // [buf][ Ah 4096 | Al 4096 | Bh 8192 | Bl 8192 ] = 24576; x2 = 49152 B
    __shared__ __align__(16) unsigned char sm[2][24576];

    const int tid  = threadIdx.x;
    const int lane = tid & 31;
    const int wid  = tid >> 5;          // 0..3
    const int wn   = wid * 32;          // warp n offset
    const size_t arow0 = (size_t)blockIdx.y * 64;
    const size_t bcol0 = (size_t)blockIdx.x * 128;

    const int ns = Kdim / 32;

    float acc[4][4][4];     // short-chain mma accumulator
    float mst[4][4][4];     // master fp32 accumulator (RN adds)
#pragma unroll
    for (int i = 0; i < 4; i++)
#pragma unroll
        for (int j = 0; j < 4; j++)
#pragma unroll
            for (int r = 0; r < 4; r++) { acc[i][j][r] = 0.0f; mst[i][j][r] = 0.0f; }

    // --- slab loader: Ah (+Al) 64x32, Bh+Bl 128x32 fp16, swizzled chunks ---
    auto load_slab = [&](int s, int buf) {
        const int k0 = s * 32;
        const uint32_t sb = smem_u32(&sm[buf][0]);
        const __half* Ahb = Ah + arow0 * Kdim + k0;
        const __half* Alb = Al + arow0 * Kdim + k0;
        const __half* Bhb = Bh + bcol0 * Kdim + k0;
        const __half* Blb = Bl + bcol0 * Kdim + k0;
        // A tiles: 64 rows x 4 chunks = 256 chunks each, 2 per thread
#pragma unroll
        for (int t = 0; t < 2; t++) {
            const int idx = tid + t * 128;          // 0..255
            const int row = idx >> 2;
            const int c   = idx & 3;
            const uint32_t off = row * 64 + ((c ^ (row & 3)) * 16);
            cp_async16(sb + off, Ahb + (size_t)row * Kdim + c * 8);
            if (NPROD == 3)
                cp_async16(sb + 4096 + off, Alb + (size_t)row * Kdim + c * 8);
        }
        // B tiles: 128 rows x 4 chunks = 512 chunks each, 4 per thread
#pragma unroll
        for (int t = 0; t < 4; t++) {
            const int idx = tid + t * 128;          // 0..511
            const int row = idx >> 2;
            const int c   = idx & 3;
            const uint32_t off = row * 64 + ((c ^ (row & 3)) * 16);
            cp_async16(sb + 8192 + off,  Bhb + (size_t)row * Kdim + c * 8);
            cp_async16(sb + 16384 + off, Blb + (size_t)row * Kdim + c * 8);
        }
        CP_COMMIT();
    };

    load_slab(0, 0);

    for (int s = 0; s < ns; s++) {
        if (s + 1 < ns) {
            load_slab(s + 1, (s + 1) & 1);
            CP_WAIT(1);
        } else {
            CP_WAIT(0);
        }
        __syncthreads();

        const uint32_t sb  = smem_u32(&sm[s & 1][0]);
        const uint32_t sAh = sb, sAl = sb + 4096;
        const uint32_t sBh = sb + 8192, sBl = sb + 16384;
        const int rl = (lane & 7) + ((lane >> 3) & 1) * 8;  // row-in-16 for ldmatrix

#pragma unroll
        for (int s16 = 0; s16 < 2; s16++) {
            const int ch = s16 * 2 + (lane >> 4);           // 16B chunk (k8 index)
            uint32_t ah[4][4], al[4][4], bh[2][4], bl[2][4];
#pragma unroll
            for (int i = 0; i < 4; i++) {
                const int row = i * 16 + rl;                // wm = 0
                const uint32_t off = row * 64 + ((ch ^ (row & 3)) * 16);
                ldm_x4(ah[i], sAh + off);
                if (NPROD == 3) ldm_x4(al[i], sAl + off);
            }
#pragma unroll
            for (int j = 0; j < 2; j++) {
                const int row = wn + j * 16 + rl;
                const uint32_t off = row * 64 + ((ch ^ (row & 3)) * 16);
                ldm_x4(bh[j], sBh + off);
                ldm_x4(bl[j], sBl + off);
            }
            // Products into the same accumulator: hh + hl (+ lh)
#pragma unroll
            for (int i = 0; i < 4; i++)
#pragma unroll
                for (int nn = 0; nn < 4; nn++) {
                    const int h = nn >> 1;
                    const uint32_t bh0 = (nn & 1) ? bh[h][1] : bh[h][0];
                    const uint32_t bh1 = (nn & 1) ? bh[h][3] : bh[h][2];
                    const uint32_t bl0 = (nn & 1) ? bl[h][1] : bl[h][0];
                    const uint32_t bl1 = (nn & 1) ? bl[h][3] : bl[h][2];
                    mma16816(acc[i][nn], ah[i], bh0, bh1);
                    mma16816(acc[i][nn], ah[i], bl0, bl1);
                    if (NPROD == 3) mma16816(acc[i][nn], al[i], bh0, bh1);
                }
        }

        // Drain every 2 slabs: master += acc (RN), acc = 0.
        if (((s & 1) == 1) || (s + 1 == ns)) {
#pragma unroll
            for (int i = 0; i < 4; i++)
#pragma unroll
                for (int j = 0; j < 4; j++)
#pragma unroll
                    for (int r = 0; r < 4; r++) {
                        mst[i][j][r] += acc[i][j][r];
                        acc[i][j][r] = 0.0f;
                    }
        }
        __syncthreads();
    }

    // --- epilogue: scale + bias; optional fp16 2-level split outputs ---
    const int mrow  = lane >> 2;
    const int ncol2 = (lane & 3) * 2;
#pragma unroll
    for (int nn = 0; nn < 4; nn++) {
        const int n = (int)bcol0 + wn + nn * 8 + ncol2;
        const float2 bv = *(const float2*)(bias + n);
#pragma unroll
        for (int i = 0; i < 4; i++) {
            const size_t m0 = arow0 + i * 16 + mrow;
            float2 o0, o1;
            o0.x = mst[i][nn][0] * scale + bv.x;
            o0.y = mst[i][nn][1] * scale + bv.y;
            o1.x = mst[i][nn][2] * scale + bv.x;
            o1.y = mst[i][nn][3] * scale + bv.y;
            *(float2*)(C + m0 * Ncols + n)       = o0;
            *(float2*)(C + (m0 + 8) * Ncols + n) = o1;
            if (Ch) {
                __half h0x = __float2half_rn(o0.x), h0y = __float2half_rn(o0.y);
                __half h1x = __float2half_rn(o1.x), h1y = __float2half_rn(o1.y);
                *(__half2*)(Ch + m0 * Ncols + n) = __halves2half2(h0x, h0y);
                *(__half2*)(Ch + (m0 + 8) * Ncols + n) = __halves2half2(h1x, h1y);
                *(__half2*)(Cl + m0 * Ncols + n) = __halves2half2(
                    __float2half_rn(o0.x - __half2float(h0x)),
                    __float2half_rn(o0.y - __half2float(h0y)));
                *(__half2*)(Cl + (m0 + 8) * Ncols + n) = __halves2half2(
                    __float2half_rn(o1.x - __half2float(h1x)),
                    __float2half_rn(o1.y - __half2float(h1y)));
            }
        }
    }
}

// ---------------------------------------------------------------------------
// Merged row-wise squared norms: rows [0, B_) from emb -> enorm,
// rows [B_, B_+K_) from CR -> cnorm. One warp per row, one launch.
// ---------------------------------------------------------------------------
__global__ void rownorm_all(const float* __restrict__ emb,
                            const float* __restrict__ CR,
                            float* __restrict__ enorm,
                            float* __restrict__ cnorm)
{
    const int gw   = (blockIdx.x * blockDim.x + threadIdx.x) >> 5;
    const int lane = threadIdx.x & 31;
    const float4* p;
    float* dst;
    if (gw < B_) {
        p = (const float4*)(emb + (size_t)gw * 256);
        dst = enorm + gw;
    } else if (gw < B_ + K_) {
        p = (const float4*)(CR + (size_t)(gw - B_) * 256);
        dst = cnorm + (gw - B_);
    } else return;
    float4 a = p[lane];
    float4 b = p[lane + 32];
    float s = a.x * a.x + a.y * a.y + a.z * a.z + a.w * a.w
            + b.x * b.x + b.y * b.y + b.z * b.z + b.w * b.w;
#pragma unroll
    for (int o = 16; o > 0; o >>= 1) s += __shfl_xor_sync(0xffffffffu, s, o);
    if (lane == 0) *dst = s;
}

// ---------------------------------------------------------------------------
// Softmin epilogue: G[b,k] = -2 e.c + ||c||^2 from the tensor GEMM.
// dist = enorm[b] + G; stable softmin over k; outWD[k,b] = dist*softmax.
// ---------------------------------------------------------------------------
__global__ __launch_bounds__(256) void softmin_lite(
    const float* __restrict__ G, const float* __restrict__ enorm,
    float* __restrict__ outWD)
{
    __shared__ float stage[128 * 65];   // 33 KB
    const int tid  = threadIdx.x;
    const int lane = tid & 31;
    const int wid  = tid >> 5;
    const int b0   = blockIdx.x * 64;

    float wd[8][8];
#pragma unroll
    for (int i = 0; i < 8; i++) {
        const int b = b0 + wid * 8 + i;
        const float en = enorm[b];
        const float* Gr = G + (size_t)b * K_;
        float dd[8];
        float m = INFINITY;
#pragma unroll
        for (int c = 0; c < 8; c++) {
            dd[c] = en + Gr[lane + 32 * c];
            m = fminf(m, dd[c]);
        }
#pragma unroll
        for (int o = 16; o > 0; o >>= 1)
            m = fminf(m, __shfl_xor_sync(0xffffffffu, m, o));

        float e[8];
        float s = 0.0f;
#pragma unroll
        for (int c = 0; c < 8; c++) {
            e[c] = expf(-ALPHA_ * (dd[c] - m));
            s += e[c];
        }
#pragma unroll
        for (int o = 16; o > 0; o >>= 1)
            s += __shfl_xor_sync(0xffffffffu, s, o);
        const float inv = 1.0f / s;
#pragma unroll
        for (int c = 0; c < 8; c++)
            wd[i][c] = dd[c] * e[c] * inv;
    }

    // stage + coalesced store in two 128-k-row halves (stage = [128][65])
#pragma unroll
    for (int hh = 0; hh < 2; hh++) {
        if (hh) __syncthreads();
#pragma unroll
        for (int i = 0; i < 8; i++)
#pragma unroll
            for (int cc = 0; cc < 4; cc++) {
                const int c = hh * 4 + cc;
                stage[(lane + 32 * c - 128 * hh) * 65 + wid * 8 + i] = wd[i][c];
            }
        __syncthreads();
#pragma unroll
        for (int t = 0; t < 8; t++) {
            const int idx = tid + t * 256;      // 0..2047
            const int k   = idx >> 4;           // 0..127
            const int c4  = idx & 15;
            float4 o;
            o.x = stage[k * 65 + c4 * 4 + 0];
            o.y = stage[k * 65 + c4 * 4 + 1];
            o.z = stage[k * 65 + c4 * 4 + 2];
            o.w = stage[k * 65 + c4 * 4 + 3];
            *(float4*)(outWD + (size_t)(128 * hh + k) * B_ + b0 + c4 * 4) = o;
        }
    }
}

// ---------------------------------------------------------------------------
// Launch
// ---------------------------------------------------------------------------
extern "C" void kernel_launch(void* const* d_in, const int* in_sizes, int n_in,
                              void* d_out, int out_size)
{
    const float* x     = (const float*)d_in[0];  // [B, D]
    const float* W_enc = (const float*)d_in[1];  // [D, K]
    const float* b_enc = (const float*)d_in[2];  // [K]
    const float* W_dec = (const float*)d_in[3];  // [K, D]
    const float* b_dec = (const float*)d_in[4];  // [D]
    const float* CR    = (const float*)d_in[5];  // [K, K]

    float* out    = (float*)d_out;
    float* outWD  = out;                         // [K, B]
    float* outRec = out + (size_t)K_ * B_;       // [B, D]

    float *emb, *dist, *en, *cn;
    __half *xh, *xl, *weh, *wel, *wdh, *wdl, *eh, *el, *crh, *crl;
    cudaGetSymbolAddress((void**)&emb,  g_emb);
    cudaGetSymbolAddress((void**)&dist, g_dist);
    cudaGetSymbolAddress((void**)&en,   g_enorm);
    cudaGetSymbolAddress((void**)&cn,   g_cnorm);
    cudaGetSymbolAddress((void**)&xh,   g_xh);
    cudaGetSymbolAddress((void**)&xl,   g_xl);
    cudaGetSymbolAddress((void**)&weh,  g_weh);
    cudaGetSymbolAddress((void**)&wel,  g_wel);
    cudaGetSymbolAddress((void**)&wdh,  g_wdh);
    cudaGetSymbolAddress((void**)&wdl,  g_wdl);
    cudaGetSymbolAddress((void**)&eh,   g_eh);
    cudaGetSymbolAddress((void**)&el,   g_el);
    cudaGetSymbolAddress((void**)&crh,  g_crh);
    cudaGetSymbolAddress((void**)&crl,  g_crl);

    // 1) all fp16 2-level splits in ONE launch (x | W_enc^T x64 | W_dec^T x16
    //    | CR x16 — pre-scaling keeps low splits fp16-normal)
    split_all<<<SPLIT_B3, 256>>>(x, W_enc, W_dec, CR,
                                 xh, xl, weh, wel, wdh, wdl, crh, crl);

    // 2) emb = x @ W_enc + b_enc  (3 products — amplified path, /64);
    //    epilogue also emits eh/el = fp16 split of emb
    hmma_gemmf<3><<<dim3(K_ / 128, B_ / 64), 128>>>(
        xh, xl, weh, wel, b_enc, emb, eh, el, D_, K_, 1.0f / 64.0f);

    // 3) norms (emb + CR in one launch)
    rownorm_all<<<(B_ + K_) / 8, 256>>>(emb, CR, en, cn);

    // 4) G = -2 e.c^T + ||c||^2 via tensor GEMM (3 products — amplified path)
    hmma_gemmf<3><<<dim3(K_ / 128, B_ / 64), 128>>>(
        eh, el, crh, crl, cn, dist, nullptr, nullptr, K_, K_, -0.125f);

    // 5) recon = emb @ W_dec + b_dec  (2 products — 1e-3 tolerance path, /16)
    hmma_gemmf<2><<<dim3(D_ / 128, B_ / 64), 128>>>(
        eh, el, wdh, wdl, b_dec, outRec, nullptr, nullptr, K_, D_, 1.0f / 16.0f);

    // 6) softmin epilogue: dist = en + G, stable softmin, transposed store
    softmin_lite<<<B_ / 64, 256>>>(dist, en, outWD);
}